// round 4
// baseline (speedup 1.0000x reference)
#include <cuda_runtime.h>
#include <cuda_fp16.h>
#include <cstdint>
#include <cstddef>

// ============================================================================
// FP4SymmetricLinear: C[8192,4096] = X[8192,4096] @ W^T[4096,4096] + bias
//
// Toolchain compiles PTX at virtual target compute_103 -> tcgen05/TMEM (the
// 'a'-suffix feature set) is unavailable. Use classic mma.sync HMMA path:
//   1) convert_x: fp32 -> fp16 scratch (g_x16)
//   2) dequant_w: packed fp4 codebook -> fp16 weights (g_w16)
//   3) GEMM: 128x128 CTA tile, BK=32, 3-stage cp.async pipeline,
//      ldmatrix.x4 + mma.sync.m16n8k16 (fp16 in, fp32 accum), bias epilogue.
// ============================================================================

#define M_TOTAL 8192
#define N_TOTAL 4096
#define K_TOTAL 4096

#define BM 128
#define BN 128
#define BK 32
#define KITERS (K_TOTAL / BK)       // 128
#define STAGES 3
#define THREADS 256

// SMEM: per stage, A[128][32] and B[128][32] fp16 with 8-half row padding
// (row stride 40 halves = 80 bytes -> conflict-free ldmatrix).
#define ROW_HALVES 40
#define ROW_BYTES  80
#define TILE_SMEM  (BM * ROW_BYTES)          // 10240 per operand tile
#define STAGE_SMEM (2 * TILE_SMEM)           // 20480
#define SMEM_TOTAL (STAGES * STAGE_SMEM)     // 61440

// Scratch (device globals: allocation-free rule compliant)
__device__ __align__(16) __half g_x16[(size_t)M_TOTAL * K_TOTAL];
__device__ __align__(16) __half g_w16[(size_t)N_TOTAL * K_TOTAL];

__device__ __constant__ float c_codebook[16] = {
    0.0f, 0.0052f, 0.6667f, 1.0f, 0.3333f, 0.5f, 0.1667f, 0.25f,
    0.0f, -0.0052f, -0.6667f, -1.0f, -0.3333f, -0.5f, -0.1667f, -0.25f
};

// ---------------------------------------------------------------------------
// PTX helpers (compute_80-era instructions only — valid at compute_103)
// ---------------------------------------------------------------------------
__device__ __forceinline__ uint32_t smem_to_u32(const void* smem_ptr) {
    uint32_t addr;
    asm("{ .reg .u64 tmp; cvta.to.shared.u64 tmp, %1; cvt.u32.u64 %0, tmp; }"
        : "=r"(addr) : "l"(smem_ptr));
    return addr;
}

#define CP_ASYNC_CG(saddr, gptr) \
    asm volatile("cp.async.cg.shared.global [%0], [%1], 16;" \
                 :: "r"(saddr), "l"(gptr) : "memory")
#define CP_COMMIT() \
    asm volatile("cp.async.commit_group;" ::: "memory")
#define CP_WAIT(n) \
    asm volatile("cp.async.wait_group %0;" :: "n"(n) : "memory")

#define LDMATRIX_X4(r0, r1, r2, r3, addr) \
    asm volatile("ldmatrix.sync.aligned.m8n8.x4.shared.b16 {%0,%1,%2,%3}, [%4];" \
                 : "=r"(r0), "=r"(r1), "=r"(r2), "=r"(r3) : "r"(addr))

#define MMA16816(d, a, b) \
    asm volatile("mma.sync.aligned.m16n8k16.row.col.f32.f16.f16.f32 " \
                 "{%0,%1,%2,%3}, {%4,%5,%6,%7}, {%8,%9}, {%0,%1,%2,%3};" \
                 : "+f"((d)[0]), "+f"((d)[1]), "+f"((d)[2]), "+f"((d)[3]) \
                 : "r"((a)[0]), "r"((a)[1]), "r"((a)[2]), "r"((a)[3]), \
                   "r"((b)[0]), "r"((b)[1]))

// ---------------------------------------------------------------------------
// Prepass 1: x fp32 -> fp16 (8 elements per thread)
// ---------------------------------------------------------------------------
__global__ void __launch_bounds__(256) convert_x_kernel(const float4* __restrict__ x4) {
    size_t i = (size_t)blockIdx.x * 256 + threadIdx.x;   // 4,194,304 threads
    float4 a = x4[2 * i];
    float4 b = x4[2 * i + 1];
    union { uint4 u; __half2 h[4]; } t;
    t.h[0] = __floats2half2_rn(a.x, a.y);
    t.h[1] = __floats2half2_rn(a.z, a.w);
    t.h[2] = __floats2half2_rn(b.x, b.y);
    t.h[3] = __floats2half2_rn(b.z, b.w);
    ((uint4*)g_x16)[i] = t.u;
}

// ---------------------------------------------------------------------------
// Prepass 2: dequant packed fp4 -> fp16 (4 packed bytes -> 8 weights/thread)
// Element 2i = high nibble of byte i, element 2i+1 = low nibble.
// block(e) = e >> 6; 8 consecutive elements of an aligned thread share a block.
// ---------------------------------------------------------------------------
__global__ void __launch_bounds__(256) dequant_w_kernel(
    const int4* __restrict__ wp4, const float* __restrict__ scale
) {
    __shared__ float cb[16];
    if (threadIdx.x < 16) cb[threadIdx.x] = c_codebook[threadIdx.x];
    __syncthreads();

    size_t i = (size_t)blockIdx.x * 256 + threadIdx.x;   // 2,097,152 threads
    int4 p = wp4[i];
    float s = __ldg(scale + (i >> 3));
    union { uint4 u; __half h[8]; } t;
    t.h[0] = __float2half_rn(cb[(p.x >> 4) & 15] * s);
    t.h[1] = __float2half_rn(cb[p.x & 15] * s);
    t.h[2] = __float2half_rn(cb[(p.y >> 4) & 15] * s);
    t.h[3] = __float2half_rn(cb[p.y & 15] * s);
    t.h[4] = __float2half_rn(cb[(p.z >> 4) & 15] * s);
    t.h[5] = __float2half_rn(cb[p.z & 15] * s);
    t.h[6] = __float2half_rn(cb[(p.w >> 4) & 15] * s);
    t.h[7] = __float2half_rn(cb[p.w & 15] * s);
    ((uint4*)g_w16)[i] = t.u;
}

// ---------------------------------------------------------------------------
// GEMM kernel
// 8 warps: 4 (M) x 2 (N); warp tile 32x64; per-thread 2x8 m16n8 accumulators.
// ---------------------------------------------------------------------------
__global__ void __launch_bounds__(THREADS) gemm_kernel(
    float* __restrict__ out, const float* __restrict__ bias
) {
    extern __shared__ char smem[];
    uint32_t smem_u32 = smem_to_u32(smem);
    int tid  = threadIdx.x;
    int wid  = tid >> 5;
    int lane = tid & 31;
    int wm   = wid & 3;          // warp row 0..3 (32 M-rows each)
    int wn   = wid >> 2;         // warp col 0..1 (64 N-cols each)

    // Rasterize: supertiles of 8 M-tiles x 32 N-tiles for L2 reuse
    int pid = blockIdx.x;                 // 0..2047
    int g   = pid >> 8;                   // 8 groups
    int rem = pid & 255;
    int mt  = (g << 3) + (rem & 7);       // 0..63
    int nt  = rem >> 3;                   // 0..31
    int m0  = mt * BM;
    int n0  = nt * BN;

    const __half* __restrict__ xA = g_x16 + (size_t)m0 * K_TOTAL;
    const __half* __restrict__ wB = g_w16 + (size_t)n0 * K_TOTAL;

    // Per-thread load coords: tile = 128 rows x 4 chunks of 16B; 512 chunks;
    // 2 chunks/thread per operand. chunk v: r = v>>2, c = v&3.
    int lr0 = tid >> 2, lc0 = tid & 3;          // v = tid
    int lr1 = (tid + 256) >> 2;                 // v = tid + 256 (lc same)

    auto issue_stage = [&](int s) {
        int kpos = s * BK;
        uint32_t sbase = smem_u32 + (s % STAGES) * STAGE_SMEM;
        // A
        CP_ASYNC_CG(sbase + lr0 * ROW_BYTES + lc0 * 16,
                    xA + (size_t)lr0 * K_TOTAL + kpos + lc0 * 8);
        CP_ASYNC_CG(sbase + lr1 * ROW_BYTES + lc0 * 16,
                    xA + (size_t)lr1 * K_TOTAL + kpos + lc0 * 8);
        // B
        CP_ASYNC_CG(sbase + TILE_SMEM + lr0 * ROW_BYTES + lc0 * 16,
                    wB + (size_t)lr0 * K_TOTAL + kpos + lc0 * 8);
        CP_ASYNC_CG(sbase + TILE_SMEM + lr1 * ROW_BYTES + lc0 * 16,
                    wB + (size_t)lr1 * K_TOTAL + kpos + lc0 * 8);
        CP_COMMIT();
    };

    float acc[2][8][4];
    #pragma unroll
    for (int i = 0; i < 2; ++i)
        #pragma unroll
        for (int j = 0; j < 8; ++j)
            #pragma unroll
            for (int k = 0; k < 4; ++k) acc[i][j][k] = 0.0f;

    issue_stage(0);
    issue_stage(1);

    // Precompute ldmatrix lane addressing
    // A: 16x16 tile; lane -> row (lane&15), k-half ((lane>>4)*8)
    int a_row_l  = lane & 15;
    int a_koff_l = (lane >> 4) * 8;
    // B: 16(n)x16(k) via x4; mat = lane>>3:
    //   n_row = (lane&7) + (mat>>1)*8, k_off = (mat&1)*8
    int b_mat    = lane >> 3;
    int b_row_l  = (lane & 7) + ((b_mat >> 1) << 3);
    int b_koff_l = (b_mat & 1) * 8;

    for (int s = 0; s < KITERS; ++s) {
        CP_WAIT(1);
        __syncthreads();

        uint32_t sbase = smem_u32 + (s % STAGES) * STAGE_SMEM;
        uint32_t aBase = sbase;
        uint32_t bBase = sbase + TILE_SMEM;

        #pragma unroll
        for (int ks = 0; ks < 2; ++ks) {         // 2 x k16 per BK=32
            uint32_t a[2][4];
            uint32_t b[8][2];
            #pragma unroll
            for (int mi = 0; mi < 2; ++mi) {
                int row = wm * 32 + mi * 16 + a_row_l;
                int col = ks * 16 + a_koff_l;
                LDMATRIX_X4(a[mi][0], a[mi][1], a[mi][2], a[mi][3],
                            aBase + row * ROW_BYTES + col * 2);
            }
            #pragma unroll
            for (int j = 0; j < 4; ++j) {
                int nrow = wn * 64 + j * 16 + b_row_l;
                int col  = ks * 16 + b_koff_l;
                LDMATRIX_X4(b[2 * j][0], b[2 * j][1],
                            b[2 * j + 1][0], b[2 * j + 1][1],
                            bBase + nrow * ROW_BYTES + col * 2);
            }
            #pragma unroll
            for (int mi = 0; mi < 2; ++mi)
                #pragma unroll
                for (int nj = 0; nj < 8; ++nj)
                    MMA16816(acc[mi][nj], a[mi], b[nj]);
        }

        if (s + 2 < KITERS) issue_stage(s + 2);
        else CP_COMMIT();   // empty group keeps wait_group counting aligned
    }

    // Epilogue: D frag mapping (m16n8): d0,d1 -> row l>>2, cols 2(l&3)+{0,1};
    // d2,d3 -> row (l>>2)+8.
    int row_base = m0 + wm * 32 + (lane >> 2);
    int col_base = n0 + wn * 64 + (lane & 3) * 2;
    #pragma unroll
    for (int mi = 0; mi < 2; ++mi) {
        #pragma unroll
        for (int nj = 0; nj < 8; ++nj) {
            int c = col_base + nj * 8;
            float2 bv = *(const float2*)(bias + c);
            #pragma unroll
            for (int h = 0; h < 2; ++h) {
                int r = row_base + mi * 16 + h * 8;
                float2 o;
                o.x = acc[mi][nj][2 * h + 0] + bv.x;
                o.y = acc[mi][nj][2 * h + 1] + bv.y;
                *(float2*)(out + (size_t)r * N_TOTAL + c) = o;
            }
        }
    }
}

// ---------------------------------------------------------------------------
// Launch
// ---------------------------------------------------------------------------
extern "C" void kernel_launch(void* const* d_in, const int* in_sizes, int n_in,
                              void* d_out, int out_size) {
    const float* x     = (const float*)d_in[0];   // [4,2048,4096] fp32
    const int*   wp    = (const int*)d_in[1];     // [8388608] int32 (1 byte each)
    const float* scale = (const float*)d_in[2];   // [262144] fp32
    const float* bias  = (const float*)d_in[3];   // [4096] fp32
    float*       out   = (float*)d_out;           // [4,2048,4096] fp32

    (void)in_sizes; (void)n_in; (void)out_size;

    convert_x_kernel<<<16384, 256>>>((const float4*)x);
    dequant_w_kernel<<<8192, 256>>>((const int4*)wp, scale);

    cudaFuncSetAttribute(gemm_kernel,
                         cudaFuncAttributeMaxDynamicSharedMemorySize, SMEM_TOTAL);
    gemm_kernel<<<(M_TOTAL / BM) * (N_TOTAL / BN), THREADS, SMEM_TOTAL>>>(out, bias);
}